// round 12
// baseline (speedup 1.0000x reference)
#include <cuda_runtime.h>
#include <cuda_bf16.h>
#include <math.h>
#include <stdint.h>

#define TT 256
#define BB 16
#define HH 512
#define VV 32000
#define NBLK 128
#define NTHR 256

// ---------------- device globals (no allocations allowed) ----------------
__device__ float g_hbuf[2][4 * BB * HH];          // double-buffered h for 4 cells
__device__ float g_y0[TT * BB * 2 * HH];          // layer-0 concat outputs
__device__ float g_y1[TT * BB * 2 * HH];          // layer-1 concat outputs (classifier input)
__device__ unsigned g_cnt;                        // full-grid barrier counter (phase boundary)
__device__ unsigned g_flags[NBLK];                // per-block step flags (distributed barrier)

// bf16 split buffers for tensor-core classifier
__device__ __nv_bfloat16 g_Yhi[4096 * 1024];
__device__ __nv_bfloat16 g_Ylo[4096 * 1024];
__device__ __nv_bfloat16 g_Whi[32000 * 1024];
__device__ __nv_bfloat16 g_Wlo[32000 * 1024];

// smem layout (floats) for rnn kernel
#define OFF_W     0                                // 32*1536 max
#define OFF_ZS    49152                            // 2 * 128 * 16 = 4096
#define OFF_GATES 53248                            // 32*16 = 512
#define OFF_BIAS  53760                            // 32
#define OFF_WIH   53792                            // 32
#define OFF_CLOC  53824                            // 128
#define SMEM_FLOATS 53952
#define SMEM_BYTES (SMEM_FLOATS * 4)               // 215,808 B

__global__ void init_kernel(const float* __restrict__ enc_h) {
    if (blockIdx.x == 0 && threadIdx.x == 0) g_cnt = 0u;
    if (blockIdx.x == 0 && threadIdx.x < NBLK) g_flags[threadIdx.x] = 0u;
    int i = blockIdx.x * blockDim.x + threadIdx.x;
    if (i < 4 * BB * HH) g_hbuf[0][i] = enc_h[i];
}

__device__ __forceinline__ float sigf(float x) { return 1.0f / (1.0f + expf(-x)); }

// ---------------- persistent recurrence kernel ----------------
__global__ __launch_bounds__(NTHR, 1) void rnn_kernel(
    const float* __restrict__ enc_c,
    const float* __restrict__ target,
    const float* __restrict__ Wih0f, const float* __restrict__ Whh0f,
    const float* __restrict__ bi0f,  const float* __restrict__ bh0f,
    const float* __restrict__ Wih0b, const float* __restrict__ Whh0b,
    const float* __restrict__ bi0b,  const float* __restrict__ bh0b,
    const float* __restrict__ Wih1f, const float* __restrict__ Whh1f,
    const float* __restrict__ bi1f,  const float* __restrict__ bh1f,
    const float* __restrict__ Wih1b, const float* __restrict__ Whh1b,
    const float* __restrict__ bi1b,  const float* __restrict__ bh1b,
    float* __restrict__ out)
{
    extern __shared__ float sm[];
    float* Wsh   = sm + OFF_W;      // [32][WS]
    float* zs    = sm + OFF_ZS;     // [2][128][16]
    float* gates = sm + OFF_GATES;  // [32][16]
    float* biasS = sm + OFF_BIAS;   // [32]
    float* wihS  = sm + OFF_WIH;    // [32]
    float* c_loc = sm + OFF_CLOC;   // [8][16]

    const int tid  = threadIdx.x;
    const int half = blockIdx.x >> 6;        // 0: forward chain, 1: backward chain
    const int u0   = (blockIdx.x & 63) * 8;  // first hidden unit owned
    const int ks   = tid & 7;                // k-slice within warp
    const int bq   = (tid >> 3) & 3;         // batch quad
    const int rid  = tid >> 5;               // warp index = row quad
    const int sk   = tid & 127;              // staging: k within chunk
    const int bh8  = (tid >> 7) * 8;         // staging: batch half (0 or 8)

    for (int ph = 0; ph < 2; ph++) {
        const int K  = ph ? 1536 : 512;
        const int WS = ph ? 1536 : 512;
        const int NC = K >> 7;               // chunks of 128
        const int cell = ph * 2 + half;
        const float* Wih = ph ? (half ? Wih1b : Wih1f) : (half ? Wih0b : Wih0f);
        const float* Whh = ph ? (half ? Whh1b : Whh1f) : (half ? Whh0b : Whh0f);
        const float* bi  = ph ? (half ? bi1b  : bi1f ) : (half ? bi0b  : bi0f );
        const float* bh  = ph ? (half ? bh1b  : bh1f ) : (half ? bh0b  : bh0f );

        // ---- stage weights into smem (persist across all T steps) ----
        if (ph == 0) {
            for (int idx = tid; idx < 32 * 512; idx += NTHR) {
                int rl = idx >> 9, k = idx & 511;
                int grow = (rl >> 3) * HH + u0 + (rl & 7);
                Wsh[rl * 512 + k] = Whh[grow * HH + k];
            }
        } else {
            for (int idx = tid; idx < 32 * 1024; idx += NTHR) {
                int rl = idx >> 10, k = idx & 1023;
                int grow = (rl >> 3) * HH + u0 + (rl & 7);
                Wsh[rl * 1536 + k] = Wih[grow * 1024 + k];
            }
            for (int idx = tid; idx < 32 * 512; idx += NTHR) {
                int rl = idx >> 9, k = idx & 511;
                int grow = (rl >> 3) * HH + u0 + (rl & 7);
                Wsh[rl * 1536 + 1024 + k] = Whh[grow * HH + k];
            }
        }
        if (tid < 32) {
            int grow = (tid >> 3) * HH + u0 + (tid & 7);
            biasS[tid] = bi[grow] + bh[grow];
            if (ph == 0) wihS[tid] = Wih[grow];   // Wih_l0 is (2048,1)
        }
        if (tid < 128) {
            int j = tid >> 4, b = tid & 15;
            c_loc[tid] = enc_c[cell * BB * HH + b * HH + u0 + j];
        }
        __syncthreads();

        for (int t = 0; t < TT; t++) {
            const int p = t & 1;
            float acc[4][4];
#pragma unroll
            for (int i = 0; i < 4; i++)
#pragma unroll
                for (int j = 0; j < 4; j++) acc[i][j] = 0.0f;

            float r[8];
            // ---- stage chunk 0 ----
            {
                const int kg = sk;   // kc = 0
#pragma unroll
                for (int j = 0; j < 8; j++) {
                    int b = bh8 + j;
                    float v;
                    if (ph == 0) {
                        v = __ldcg(&g_hbuf[p][cell * (BB * HH) + b * HH + kg]);
                    } else {
                        v = __ldcg(&g_y0[t * (BB * 2 * HH) + b * (2 * HH) + kg]);
                    }
                    r[j] = v;
                }
                float* zw = zs + sk * 16 + bh8;
                *(float4*)zw       = make_float4(r[0], r[1], r[2], r[3]);
                *(float4*)(zw + 4) = make_float4(r[4], r[5], r[6], r[7]);
            }
            __syncthreads();

            for (int c = 0; c < NC; c++) {
                // prefetch chunk c+1 into registers (L2 latency hidden by compute)
                if (c + 1 < NC) {
                    const int kg = (c + 1) * 128 + sk;
#pragma unroll
                    for (int j = 0; j < 8; j++) {
                        int b = bh8 + j;
                        float v;
                        if (ph == 0) {
                            v = __ldcg(&g_hbuf[p][cell * (BB * HH) + b * HH + kg]);
                        } else if (kg < 1024) {
                            v = __ldcg(&g_y0[t * (BB * 2 * HH) + b * (2 * HH) + kg]);
                        } else {
                            v = __ldcg(&g_hbuf[p][cell * (BB * HH) + b * HH + (kg - 1024)]);
                        }
                        r[j] = v;
                    }
                }

                // compute chunk c from buffer c&1
                {
                    const float* zb = zs + (c & 1) * 2048;
                    const float* wp = &Wsh[(rid * 4) * WS + c * 128 + ks];
#pragma unroll
                    for (int kk = 0; kk < 128; kk += 8) {
                        float w0 = wp[0 * WS + kk];
                        float w1 = wp[1 * WS + kk];
                        float w2 = wp[2 * WS + kk];
                        float w3 = wp[3 * WS + kk];
                        const float4 z4 = *(const float4*)&zb[(kk + ks) * 16 + bq * 4];
                        acc[0][0] += w0 * z4.x; acc[0][1] += w0 * z4.y; acc[0][2] += w0 * z4.z; acc[0][3] += w0 * z4.w;
                        acc[1][0] += w1 * z4.x; acc[1][1] += w1 * z4.y; acc[1][2] += w1 * z4.z; acc[1][3] += w1 * z4.w;
                        acc[2][0] += w2 * z4.x; acc[2][1] += w2 * z4.y; acc[2][2] += w2 * z4.z; acc[2][3] += w2 * z4.w;
                        acc[3][0] += w3 * z4.x; acc[3][1] += w3 * z4.y; acc[3][2] += w3 * z4.z; acc[3][3] += w3 * z4.w;
                    }
                }

                if (c + 1 < NC) {
                    float* zw = zs + ((c + 1) & 1) * 2048 + sk * 16 + bh8;
                    *(float4*)zw       = make_float4(r[0], r[1], r[2], r[3]);
                    *(float4*)(zw + 4) = make_float4(r[4], r[5], r[6], r[7]);
                }
                __syncthreads();
            }

            // reduce the 8-way k-split inside each warp (ks lives in lane bits 0-2)
#pragma unroll
            for (int i = 0; i < 4; i++)
#pragma unroll
                for (int j = 0; j < 4; j++) {
                    float v = acc[i][j];
                    v += __shfl_xor_sync(0xffffffffu, v, 1);
                    v += __shfl_xor_sync(0xffffffffu, v, 2);
                    v += __shfl_xor_sync(0xffffffffu, v, 4);
                    if (ks == 0) gates[(rid * 4 + i) * 16 + (bq * 4 + j)] = v;
                }
            __syncthreads();

            if (tid < 128) {
                int j = tid >> 4, b = tid & 15;
                float gi = gates[(0  + j) * 16 + b] + biasS[j];
                float gf = gates[(8  + j) * 16 + b] + biasS[8 + j];
                float gg = gates[(16 + j) * 16 + b] + biasS[16 + j];
                float go = gates[(24 + j) * 16 + b] + biasS[24 + j];
                if (ph == 0) {
                    float x = target[b * TT + t];
                    gi += x * wihS[j];
                    gf += x * wihS[8 + j];
                    gg += x * wihS[16 + j];
                    go += x * wihS[24 + j];
                }
                float cprev = c_loc[tid];
                float cn = sigf(gf) * cprev + sigf(gi) * tanhf(gg);
                float hn = sigf(go) * tanhf(cn);
                c_loc[tid] = cn;
                int u = u0 + j;
                g_hbuf[p ^ 1][cell * (BB * HH) + b * HH + u] = hn;
                float* ybuf = ph ? g_y1 : g_y0;
                ybuf[t * (BB * 2 * HH) + b * (2 * HH) + half * HH + u] = hn;
                if (t == TT - 1) {
                    long hoff = (long)BB * TT * VV;
                    out[hoff + cell * (BB * HH) + b * HH + u] = hn;
                    out[hoff + 4 * BB * HH + cell * (BB * HH) + b * HH + u] = cn;
                }
            }

            // ---- distributed flag barrier across the 64 blocks of this chain ----
            __syncthreads();
            {
                const unsigned tgt = (unsigned)(ph * TT + t + 1);
                if (tid == 0) {
                    __threadfence();
                    *((volatile unsigned*)&g_flags[half * 64 + (blockIdx.x & 63)]) = tgt;
                }
                if (tid < 64) {
                    volatile unsigned* f = (volatile unsigned*)&g_flags[half * 64 + tid];
                    while (*f < tgt) { }
                }
            }
            __syncthreads();
        }

        // ---- full-grid barrier at phase boundary (y0 must be complete) ----
        if (ph == 0) {
            if (tid == 0) {
                __threadfence();
                atomicAdd(&g_cnt, 1u);
                while (*((volatile unsigned*)&g_cnt) < NBLK) __nanosleep(64);
            }
            __syncthreads();
        }
    }
}

// ================= bf16 split conversion =================
__device__ __forceinline__ void split2(float x, __nv_bfloat16& h, __nv_bfloat16& l) {
    h = __float2bfloat16(x);
    l = __float2bfloat16(x - __bfloat162float(h));
}

__global__ void convert_w_kernel(const float* __restrict__ W) {
    size_t i = (size_t)blockIdx.x * 256 + threadIdx.x;   // quad index
    size_t base = i * 4;
    float4 v = *(const float4*)(W + base);
    __nv_bfloat16 h0, h1, h2, h3, l0, l1, l2, l3;
    split2(v.x, h0, l0); split2(v.y, h1, l1);
    split2(v.z, h2, l2); split2(v.w, h3, l3);
    ushort4 hs, ls;
    hs.x = __bfloat16_as_ushort(h0); hs.y = __bfloat16_as_ushort(h1);
    hs.z = __bfloat16_as_ushort(h2); hs.w = __bfloat16_as_ushort(h3);
    ls.x = __bfloat16_as_ushort(l0); ls.y = __bfloat16_as_ushort(l1);
    ls.z = __bfloat16_as_ushort(l2); ls.w = __bfloat16_as_ushort(l3);
    *(ushort4*)(g_Whi + base) = hs;
    *(ushort4*)(g_Wlo + base) = ls;
}

__global__ void convert_y_kernel() {
    size_t i = (size_t)blockIdx.x * 256 + threadIdx.x;
    size_t base = i * 4;
    float4 v = *(const float4*)(g_y1 + base);
    __nv_bfloat16 h0, h1, h2, h3, l0, l1, l2, l3;
    split2(v.x, h0, l0); split2(v.y, h1, l1);
    split2(v.z, h2, l2); split2(v.w, h3, l3);
    ushort4 hs, ls;
    hs.x = __bfloat16_as_ushort(h0); hs.y = __bfloat16_as_ushort(h1);
    hs.z = __bfloat16_as_ushort(h2); hs.w = __bfloat16_as_ushort(h3);
    ls.x = __bfloat16_as_ushort(l0); ls.y = __bfloat16_as_ushort(l1);
    ls.z = __bfloat16_as_ushort(l2); ls.w = __bfloat16_as_ushort(l3);
    *(ushort4*)(g_Yhi + base) = hs;
    *(ushort4*)(g_Ylo + base) = ls;
}

// ================= mma.sync bf16 classifier GEMM (R10 proven config) =================
// C[4096, 32000] = Yhi*Whi^T + Ylo*Whi^T + Yhi*Wlo^T  (48 K-tiles of 64 = 3 x 1024)
// CTA tile 128x128, BK=64 bf16 (128B rows, SW128 swizzle), 3-stage cp.async pipeline.
// 8 warps = 4(m) x 2(n); warp tile 32x64; 98KB smem -> 2 CTAs/SM.
// Raster: blockIdx.x = m (32), blockIdx.y = n (250): wave shares each W tile in L2.

#define CLS_NKT 48
#define CLS_STG_BYTES 32768        // A 16KB + B 16KB
#define CLS_STAGES 3
#define OFF_CBIAS (CLS_STAGES * CLS_STG_BYTES)       // 98304
#define SMEM_CLS  (OFF_CBIAS + 128 * 4)

__device__ __forceinline__ uint32_t smem_u32(const void* p) {
    uint32_t a;
    asm("{ .reg .u64 t; cvta.to.shared.u64 t, %1; cvt.u32.u64 %0, t; }" : "=r"(a) : "l"(p));
    return a;
}
__device__ __forceinline__ uint32_t swz(uint32_t off) {
    return off ^ ((off >> 3) & 0x70);
}
__device__ __forceinline__ void cp16(uint32_t saddr, const void* g) {
    asm volatile("cp.async.cg.shared.global [%0], [%1], 16;" :: "r"(saddr), "l"(g));
}
__device__ __forceinline__ void cp_commit() { asm volatile("cp.async.commit_group;" ::: "memory"); }
template <int N> __device__ __forceinline__ void cp_wait() {
    asm volatile("cp.async.wait_group %0;" :: "n"(N) : "memory");
}
__device__ __forceinline__ void ldm_x4(uint32_t addr, uint32_t& r0, uint32_t& r1,
                                       uint32_t& r2, uint32_t& r3) {
    asm volatile("ldmatrix.sync.aligned.m8n8.x4.shared.b16 {%0,%1,%2,%3}, [%4];"
                 : "=r"(r0), "=r"(r1), "=r"(r2), "=r"(r3) : "r"(addr));
}
__device__ __forceinline__ void mma16816(float* d, const uint32_t* a, uint32_t b0, uint32_t b1) {
    asm volatile(
        "mma.sync.aligned.m16n8k16.row.col.f32.bf16.bf16.f32 "
        "{%0,%1,%2,%3}, {%4,%5,%6,%7}, {%8,%9}, {%0,%1,%2,%3};"
        : "+f"(d[0]), "+f"(d[1]), "+f"(d[2]), "+f"(d[3])
        : "r"(a[0]), "r"(a[1]), "r"(a[2]), "r"(a[3]), "r"(b0), "r"(b1));
}

__device__ __forceinline__ void cls_issue_loads(uint32_t sbase, int kt, int m0, int n0, int tid)
{
    const int pass = kt >> 4;
    const int k0 = (kt & 15) * 64;
    const __nv_bfloat16* Ap = (pass == 1) ? g_Ylo : g_Yhi;
    const __nv_bfloat16* Bp = (pass == 2) ? g_Wlo : g_Whi;
    const uint32_t sA = sbase + (uint32_t)(kt % CLS_STAGES) * CLS_STG_BYTES;
    const uint32_t sB = sA + 16384;
#pragma unroll
    for (int it = 0; it < 4; it++) {           // A: 128 rows x 8 chunks of 16B
        int i = it * 256 + tid;
        int row = i >> 3, q = i & 7;
        uint32_t off = (uint32_t)(row * 128 + q * 16);
        cp16(sA + swz(off), Ap + (size_t)(m0 + row) * 1024 + k0 + q * 8);
    }
#pragma unroll
    for (int it = 0; it < 4; it++) {           // B: 128 rows x 8 chunks of 16B
        int i = it * 256 + tid;
        int row = i >> 3, q = i & 7;
        uint32_t off = (uint32_t)(row * 128 + q * 16);
        cp16(sB + swz(off), Bp + (size_t)(n0 + row) * 1024 + k0 + q * 8);
    }
}

__global__ __launch_bounds__(256) void cls_tc_kernel(
    const float* __restrict__ bc, float* __restrict__ out)
{
    extern __shared__ char smc[];
    const uint32_t sbase = smem_u32(smc);
    const int tid = threadIdx.x;
    const int l   = tid & 31;
    const int w   = tid >> 5;
    const int m0c = blockIdx.x * 128;
    const int n0c = blockIdx.y * 128;
    float* biasS = (float*)(smc + OFF_CBIAS);

    if (tid < 128) biasS[tid] = bc[n0c + tid];

    const int wm = (w & 3) * 32;   // warp m base in CTA tile
    const int wn = (w >> 2) * 64;  // warp n base in CTA tile

    float acc[2][8][4];
#pragma unroll
    for (int mi = 0; mi < 2; mi++)
#pragma unroll
        for (int ni = 0; ni < 8; ni++)
#pragma unroll
            for (int q = 0; q < 4; q++) acc[mi][ni][q] = 0.0f;

    cls_issue_loads(sbase, 0, m0c, n0c, tid); cp_commit();
    cls_issue_loads(sbase, 1, m0c, n0c, tid); cp_commit();

    // precomputed intra-tile ldmatrix offsets (lane-dependent, k-chunk added in loop)
    const uint32_t aRow = (uint32_t)(((l >> 3) & 1) * 8 + (l & 7));   // + mi*16 + wm
    const uint32_t aCol = (uint32_t)((l >> 4) * 16);
    const uint32_t bRow = (uint32_t)((l >> 4) * 8 + (l & 7));         // + ng*16 + wn
    const uint32_t bCol = (uint32_t)(((l >> 3) & 1) * 16);

    for (int kt = 0; kt < CLS_NKT; kt++) {
        if (kt + 2 < CLS_NKT) {
            cls_issue_loads(sbase, kt + 2, m0c, n0c, tid);
            cp_commit();
            cp_wait<2>();
        } else if (kt + 1 < CLS_NKT) {
            cp_wait<1>();
        } else {
            cp_wait<0>();
        }
        __syncthreads();

        const uint32_t sA = sbase + (uint32_t)(kt % CLS_STAGES) * CLS_STG_BYTES;
        const uint32_t sB = sA + 16384;
#pragma unroll
        for (int ksi = 0; ksi < 4; ksi++) {
            uint32_t a[2][4];
#pragma unroll
            for (int mi = 0; mi < 2; mi++) {
                uint32_t off = (uint32_t)(wm + mi * 16 + aRow) * 128 + (uint32_t)(ksi * 32) + aCol;
                ldm_x4(sA + swz(off), a[mi][0], a[mi][1], a[mi][2], a[mi][3]);
            }
            uint32_t bf[4][4];
#pragma unroll
            for (int ng = 0; ng < 4; ng++) {
                uint32_t off = (uint32_t)(wn + ng * 16 + bRow) * 128 + (uint32_t)(ksi * 32) + bCol;
                ldm_x4(sB + swz(off), bf[ng][0], bf[ng][1], bf[ng][2], bf[ng][3]);
            }
#pragma unroll
            for (int mi = 0; mi < 2; mi++)
#pragma unroll
                for (int ng = 0; ng < 4; ng++) {
                    mma16816(acc[mi][ng * 2 + 0], a[mi], bf[ng][0], bf[ng][1]);
                    mma16816(acc[mi][ng * 2 + 1], a[mi], bf[ng][2], bf[ng][3]);
                }
        }
        __syncthreads();
    }

    // epilogue: bias + scatter into (B, T, V); C row m = t*16 + b
#pragma unroll
    for (int mi = 0; mi < 2; mi++) {
#pragma unroll
        for (int ni = 0; ni < 8; ni++) {
            int nloc = wn + ni * 8 + (l & 3) * 2;
            int n = n0c + nloc;
            float bx = biasS[nloc], by = biasS[nloc + 1];
            int m1 = m0c + wm + mi * 16 + (l >> 2);
            int m2 = m1 + 8;
            {
                int t = m1 >> 4, b = m1 & 15;
                float2 v; v.x = acc[mi][ni][0] + bx; v.y = acc[mi][ni][1] + by;
                *(float2*)&out[(size_t)b * ((size_t)TT * VV) + (size_t)t * VV + n] = v;
            }
            {
                int t = m2 >> 4, b = m2 & 15;
                float2 v; v.x = acc[mi][ni][2] + bx; v.y = acc[mi][ni][3] + by;
                *(float2*)&out[(size_t)b * ((size_t)TT * VV) + (size_t)t * VV + n] = v;
            }
        }
    }
}

// ---------------- launch ----------------
extern "C" void kernel_launch(void* const* d_in, const int* in_sizes, int n_in,
                              void* d_out, int out_size)
{
    const float* enc_h  = (const float*)d_in[0];
    const float* enc_c  = (const float*)d_in[1];
    const float* target = (const float*)d_in[2];
    const float* Wih0f = (const float*)d_in[3];
    const float* Whh0f = (const float*)d_in[4];
    const float* bi0f  = (const float*)d_in[5];
    const float* bh0f  = (const float*)d_in[6];
    const float* Wih0b = (const float*)d_in[7];
    const float* Whh0b = (const float*)d_in[8];
    const float* bi0b  = (const float*)d_in[9];
    const float* bh0b  = (const float*)d_in[10];
    const float* Wih1f = (const float*)d_in[11];
    const float* Whh1f = (const float*)d_in[12];
    const float* bi1f  = (const float*)d_in[13];
    const float* bh1f  = (const float*)d_in[14];
    const float* Wih1b = (const float*)d_in[15];
    const float* Whh1b = (const float*)d_in[16];
    const float* bi1b  = (const float*)d_in[17];
    const float* bh1b  = (const float*)d_in[18];
    const float* Wcls  = (const float*)d_in[19];
    const float* bcls  = (const float*)d_in[20];
    float* out = (float*)d_out;

    cudaFuncSetAttribute(rnn_kernel, cudaFuncAttributeMaxDynamicSharedMemorySize, SMEM_BYTES);
    cudaFuncSetAttribute(cls_tc_kernel, cudaFuncAttributeMaxDynamicSharedMemorySize, SMEM_CLS);

    init_kernel<<<64, 512>>>(enc_h);
    convert_w_kernel<<<32000, 256>>>(Wcls);           // 32000*1024 f32 -> hi/lo bf16
    rnn_kernel<<<NBLK, NTHR, SMEM_BYTES>>>(
        enc_c, target,
        Wih0f, Whh0f, bi0f, bh0f,
        Wih0b, Whh0b, bi0b, bh0b,
        Wih1f, Whh1f, bi1f, bh1f,
        Wih1b, Whh1b, bi1b, bh1b,
        out);
    convert_y_kernel<<<4096, 256>>>();                // g_y1 -> hi/lo bf16
    dim3 g((TT * BB) / 128, VV / 128);                // (32, 250): m fastest
    cls_tc_kernel<<<g, 256, SMEM_CLS>>>(bcls, out);
}

// round 13
// speedup vs baseline: 1.2942x; 1.2942x over previous
#include <cuda_runtime.h>
#include <cuda_bf16.h>
#include <math.h>
#include <stdint.h>

#define TT 256
#define BB 16
#define HH 512
#define VV 32000
#define NBLK 128
#define NTHR 256

// ---------------- device globals (no allocations allowed) ----------------
__device__ float g_hbuf[2][4 * BB * HH];          // double-buffered h for 4 cells
__device__ float g_y0[TT * BB * 2 * HH];          // layer-0 concat outputs (fp32, rnn-internal)
__device__ unsigned g_cnt;                        // full-grid barrier counter (phase boundary)
__device__ unsigned g_cnt_half[2];                // per-chain step-barrier counters

// bf16 split buffers for tensor-core classifier
__device__ __nv_bfloat16 g_Yhi[4096 * 1024];
__device__ __nv_bfloat16 g_Ylo[4096 * 1024];
__device__ __nv_bfloat16 g_Whi[32000 * 1024];
__device__ __nv_bfloat16 g_Wlo[32000 * 1024];

// smem layout (floats) for rnn kernel
#define OFF_W     0                                // 32*1536 max
#define OFF_ZS    49152                            // 2 * 128 * 16 = 4096
#define OFF_GATES 53248                            // 32*16 = 512
#define OFF_BIAS  53760                            // 32
#define OFF_WIH   53792                            // 32
#define OFF_CLOC  53824                            // 128
#define SMEM_FLOATS 53952
#define SMEM_BYTES (SMEM_FLOATS * 4)               // 215,808 B

__device__ __forceinline__ float sigf(float x) {
    return __fdividef(1.0f, 1.0f + __expf(-x));
}
__device__ __forceinline__ float tanhf_fast(float x) {
    // 1 - 2/(e^{2x}+1): exact limits at +-inf, MUFU-based, rel err ~1e-7
    return 1.0f - __fdividef(2.0f, __expf(2.0f * x) + 1.0f);
}

// ---------------- persistent recurrence kernel ----------------
__global__ __launch_bounds__(NTHR, 1) void rnn_kernel(
    const float* __restrict__ enc_h,
    const float* __restrict__ enc_c,
    const float* __restrict__ target,
    const float* __restrict__ Wih0f, const float* __restrict__ Whh0f,
    const float* __restrict__ bi0f,  const float* __restrict__ bh0f,
    const float* __restrict__ Wih0b, const float* __restrict__ Whh0b,
    const float* __restrict__ bi0b,  const float* __restrict__ bh0b,
    const float* __restrict__ Wih1f, const float* __restrict__ Whh1f,
    const float* __restrict__ bi1f,  const float* __restrict__ bh1f,
    const float* __restrict__ Wih1b, const float* __restrict__ Whh1b,
    const float* __restrict__ bi1b,  const float* __restrict__ bh1b,
    float* __restrict__ out)
{
    extern __shared__ float sm[];
    float* Wsh   = sm + OFF_W;      // [32][WS]
    float* zs    = sm + OFF_ZS;     // [2][128][16]
    float* gates = sm + OFF_GATES;  // [32][16]
    float* biasS = sm + OFF_BIAS;   // [32]
    float* wihS  = sm + OFF_WIH;    // [32]
    float* c_loc = sm + OFF_CLOC;   // [8][16]

    const int tid  = threadIdx.x;
    const int half = blockIdx.x >> 6;        // 0: forward chain, 1: backward chain
    const int u0   = (blockIdx.x & 63) * 8;  // first hidden unit owned
    const int ks   = tid & 7;                // k-slice within warp
    const int bq   = (tid >> 3) & 3;         // batch quad
    const int rid  = tid >> 5;               // warp index = row quad
    const int sk   = tid & 127;              // staging: k within chunk
    const int bh8  = (tid >> 7) * 8;         // staging: batch half (0 or 8)

    unsigned bar_target = 0;

    for (int ph = 0; ph < 2; ph++) {
        const int K  = ph ? 1536 : 512;
        const int WS = ph ? 1536 : 512;
        const int NC = K >> 7;               // chunks of 128
        const int cell = ph * 2 + half;
        const float* Wih = ph ? (half ? Wih1b : Wih1f) : (half ? Wih0b : Wih0f);
        const float* Whh = ph ? (half ? Whh1b : Whh1f) : (half ? Whh0b : Whh0f);
        const float* bi  = ph ? (half ? bi1b  : bi1f ) : (half ? bi0b  : bi0f );
        const float* bh  = ph ? (half ? bh1b  : bh1f ) : (half ? bh0b  : bh0f );

        // ---- stage weights into smem (persist across all T steps) ----
        if (ph == 0) {
            for (int idx = tid; idx < 32 * 512; idx += NTHR) {
                int rl = idx >> 9, k = idx & 511;
                int grow = (rl >> 3) * HH + u0 + (rl & 7);
                Wsh[rl * 512 + k] = Whh[grow * HH + k];
            }
        } else {
            for (int idx = tid; idx < 32 * 1024; idx += NTHR) {
                int rl = idx >> 10, k = idx & 1023;
                int grow = (rl >> 3) * HH + u0 + (rl & 7);
                Wsh[rl * 1536 + k] = Wih[grow * 1024 + k];
            }
            for (int idx = tid; idx < 32 * 512; idx += NTHR) {
                int rl = idx >> 9, k = idx & 511;
                int grow = (rl >> 3) * HH + u0 + (rl & 7);
                Wsh[rl * 1536 + 1024 + k] = Whh[grow * HH + k];
            }
        }
        if (tid < 32) {
            int grow = (tid >> 3) * HH + u0 + (tid & 7);
            biasS[tid] = bi[grow] + bh[grow];
            if (ph == 0) wihS[tid] = Wih[grow];   // Wih_l0 is (2048,1)
        }
        if (tid < 128) {
            int j = tid >> 4, b = tid & 15;
            c_loc[tid] = enc_c[cell * BB * HH + b * HH + u0 + j];
        }
        __syncthreads();

        for (int t = 0; t < TT; t++) {
            const int p = t & 1;
            // at t==0 the previous h is the encoder state (same [cell][b][k] layout)
            const float* hsrc = (t == 0) ? enc_h : g_hbuf[p];

            float acc[4][4];
#pragma unroll
            for (int i = 0; i < 4; i++)
#pragma unroll
                for (int j = 0; j < 4; j++) acc[i][j] = 0.0f;

            float r[8];
            // ---- stage chunk 0 ----
            {
                const int kg = sk;   // kc = 0
#pragma unroll
                for (int j = 0; j < 8; j++) {
                    int b = bh8 + j;
                    float v;
                    if (ph == 0) {
                        v = __ldcg(&hsrc[cell * (BB * HH) + b * HH + kg]);
                    } else {
                        v = __ldcg(&g_y0[t * (BB * 2 * HH) + b * (2 * HH) + kg]);
                    }
                    r[j] = v;
                }
                float* zw = zs + sk * 16 + bh8;
                *(float4*)zw       = make_float4(r[0], r[1], r[2], r[3]);
                *(float4*)(zw + 4) = make_float4(r[4], r[5], r[6], r[7]);
            }
            __syncthreads();

            for (int c = 0; c < NC; c++) {
                // prefetch chunk c+1 into registers (L2 latency hidden by compute)
                if (c + 1 < NC) {
                    const int kg = (c + 1) * 128 + sk;
#pragma unroll
                    for (int j = 0; j < 8; j++) {
                        int b = bh8 + j;
                        float v;
                        if (ph == 0) {
                            v = __ldcg(&hsrc[cell * (BB * HH) + b * HH + kg]);
                        } else if (kg < 1024) {
                            v = __ldcg(&g_y0[t * (BB * 2 * HH) + b * (2 * HH) + kg]);
                        } else {
                            v = __ldcg(&hsrc[cell * (BB * HH) + b * HH + (kg - 1024)]);
                        }
                        r[j] = v;
                    }
                }

                // compute chunk c from buffer c&1
                {
                    const float* zb = zs + (c & 1) * 2048;
                    const float* wp = &Wsh[(rid * 4) * WS + c * 128 + ks];
#pragma unroll
                    for (int kk = 0; kk < 128; kk += 8) {
                        float w0 = wp[0 * WS + kk];
                        float w1 = wp[1 * WS + kk];
                        float w2 = wp[2 * WS + kk];
                        float w3 = wp[3 * WS + kk];
                        const float4 z4 = *(const float4*)&zb[(kk + ks) * 16 + bq * 4];
                        acc[0][0] += w0 * z4.x; acc[0][1] += w0 * z4.y; acc[0][2] += w0 * z4.z; acc[0][3] += w0 * z4.w;
                        acc[1][0] += w1 * z4.x; acc[1][1] += w1 * z4.y; acc[1][2] += w1 * z4.z; acc[1][3] += w1 * z4.w;
                        acc[2][0] += w2 * z4.x; acc[2][1] += w2 * z4.y; acc[2][2] += w2 * z4.z; acc[2][3] += w2 * z4.w;
                        acc[3][0] += w3 * z4.x; acc[3][1] += w3 * z4.y; acc[3][2] += w3 * z4.z; acc[3][3] += w3 * z4.w;
                    }
                }

                if (c + 1 < NC) {
                    float* zw = zs + ((c + 1) & 1) * 2048 + sk * 16 + bh8;
                    *(float4*)zw       = make_float4(r[0], r[1], r[2], r[3]);
                    *(float4*)(zw + 4) = make_float4(r[4], r[5], r[6], r[7]);
                }
                __syncthreads();
            }

            // reduce the 8-way k-split inside each warp (ks lives in lane bits 0-2)
#pragma unroll
            for (int i = 0; i < 4; i++)
#pragma unroll
                for (int j = 0; j < 4; j++) {
                    float v = acc[i][j];
                    v += __shfl_xor_sync(0xffffffffu, v, 1);
                    v += __shfl_xor_sync(0xffffffffu, v, 2);
                    v += __shfl_xor_sync(0xffffffffu, v, 4);
                    if (ks == 0) gates[(rid * 4 + i) * 16 + (bq * 4 + j)] = v;
                }
            __syncthreads();

            if (tid < 128) {
                int j = tid >> 4, b = tid & 15;
                float gi = gates[(0  + j) * 16 + b] + biasS[j];
                float gf = gates[(8  + j) * 16 + b] + biasS[8 + j];
                float gg = gates[(16 + j) * 16 + b] + biasS[16 + j];
                float go = gates[(24 + j) * 16 + b] + biasS[24 + j];
                if (ph == 0) {
                    float x = target[b * TT + t];
                    gi += x * wihS[j];
                    gf += x * wihS[8 + j];
                    gg += x * wihS[16 + j];
                    go += x * wihS[24 + j];
                }
                float cprev = c_loc[tid];
                float cn = sigf(gf) * cprev + sigf(gi) * tanhf_fast(gg);
                float hn = sigf(go) * tanhf_fast(cn);
                c_loc[tid] = cn;
                int u = u0 + j;
                g_hbuf[p ^ 1][cell * (BB * HH) + b * HH + u] = hn;
                if (ph == 0) {
                    g_y0[t * (BB * 2 * HH) + b * (2 * HH) + half * HH + u] = hn;
                } else {
                    // fused bf16 hi/lo split of y1 for the classifier
                    __nv_bfloat16 hh = __float2bfloat16(hn);
                    __nv_bfloat16 hl = __float2bfloat16(hn - __bfloat162float(hh));
                    size_t yi = (size_t)(t * 16 + b) * 1024 + (size_t)(half * HH + u);
                    g_Yhi[yi] = hh;
                    g_Ylo[yi] = hl;
                }
                if (t == TT - 1) {
                    long hoff = (long)BB * TT * VV;
                    out[hoff + cell * (BB * HH) + b * HH + u] = hn;
                    out[hoff + 4 * BB * HH + cell * (BB * HH) + b * HH + u] = cn;
                }
            }

            // ---- throttled counter barrier across the 64 blocks of this chain ----
            __syncthreads();
            bar_target += 64;
            if (tid == 0) {
                __threadfence();
                atomicAdd(&g_cnt_half[half], 1u);
                while (*((volatile unsigned*)&g_cnt_half[half]) < bar_target) __nanosleep(32);
            }
            __syncthreads();
        }

        // ---- full-grid barrier at phase boundary (y0 must be complete) ----
        if (ph == 0) {
            if (tid == 0) {
                __threadfence();
                atomicAdd(&g_cnt, 1u);
                while (*((volatile unsigned*)&g_cnt) < NBLK) __nanosleep(64);
            }
            __syncthreads();
        }
    }
}

// ================= bf16 split conversion (weights) + barrier-counter reset =================
__device__ __forceinline__ void split2(float x, __nv_bfloat16& h, __nv_bfloat16& l) {
    h = __float2bfloat16(x);
    l = __float2bfloat16(x - __bfloat162float(h));
}

__global__ void convert_w_kernel(const float* __restrict__ W) {
    if (blockIdx.x == 0 && threadIdx.x == 0) {
        g_cnt = 0u;
        g_cnt_half[0] = 0u;
        g_cnt_half[1] = 0u;
    }
    size_t i = (size_t)blockIdx.x * 256 + threadIdx.x;   // quad index
    size_t base = i * 4;
    float4 v = *(const float4*)(W + base);
    __nv_bfloat16 h0, h1, h2, h3, l0, l1, l2, l3;
    split2(v.x, h0, l0); split2(v.y, h1, l1);
    split2(v.z, h2, l2); split2(v.w, h3, l3);
    ushort4 hs, ls;
    hs.x = __bfloat16_as_ushort(h0); hs.y = __bfloat16_as_ushort(h1);
    hs.z = __bfloat16_as_ushort(h2); hs.w = __bfloat16_as_ushort(h3);
    ls.x = __bfloat16_as_ushort(l0); ls.y = __bfloat16_as_ushort(l1);
    ls.z = __bfloat16_as_ushort(l2); ls.w = __bfloat16_as_ushort(l3);
    *(ushort4*)(g_Whi + base) = hs;
    *(ushort4*)(g_Wlo + base) = ls;
}

// ================= mma.sync bf16 classifier GEMM (R10 proven config) =================
// C[4096, 32000] = Yhi*Whi^T + Ylo*Whi^T + Yhi*Wlo^T  (48 K-tiles of 64 = 3 x 1024)
// CTA tile 128x128, BK=64 bf16 (128B rows, SW128 swizzle), 3-stage cp.async pipeline.
// 8 warps = 4(m) x 2(n); warp tile 32x64; 98KB smem -> 2 CTAs/SM.
// Raster: blockIdx.x = m (32), blockIdx.y = n (250): wave shares each W tile in L2.

#define CLS_NKT 48
#define CLS_STG_BYTES 32768        // A 16KB + B 16KB
#define CLS_STAGES 3
#define OFF_CBIAS (CLS_STAGES * CLS_STG_BYTES)       // 98304
#define SMEM_CLS  (OFF_CBIAS + 128 * 4)

__device__ __forceinline__ uint32_t smem_u32(const void* p) {
    uint32_t a;
    asm("{ .reg .u64 t; cvta.to.shared.u64 t, %1; cvt.u32.u64 %0, t; }" : "=r"(a) : "l"(p));
    return a;
}
__device__ __forceinline__ uint32_t swz(uint32_t off) {
    return off ^ ((off >> 3) & 0x70);
}
__device__ __forceinline__ void cp16(uint32_t saddr, const void* g) {
    asm volatile("cp.async.cg.shared.global [%0], [%1], 16;" :: "r"(saddr), "l"(g));
}
__device__ __forceinline__ void cp_commit() { asm volatile("cp.async.commit_group;" ::: "memory"); }
template <int N> __device__ __forceinline__ void cp_wait() {
    asm volatile("cp.async.wait_group %0;" :: "n"(N) : "memory");
}
__device__ __forceinline__ void ldm_x4(uint32_t addr, uint32_t& r0, uint32_t& r1,
                                       uint32_t& r2, uint32_t& r3) {
    asm volatile("ldmatrix.sync.aligned.m8n8.x4.shared.b16 {%0,%1,%2,%3}, [%4];"
                 : "=r"(r0), "=r"(r1), "=r"(r2), "=r"(r3) : "r"(addr));
}
__device__ __forceinline__ void mma16816(float* d, const uint32_t* a, uint32_t b0, uint32_t b1) {
    asm volatile(
        "mma.sync.aligned.m16n8k16.row.col.f32.bf16.bf16.f32 "
        "{%0,%1,%2,%3}, {%4,%5,%6,%7}, {%8,%9}, {%0,%1,%2,%3};"
        : "+f"(d[0]), "+f"(d[1]), "+f"(d[2]), "+f"(d[3])
        : "r"(a[0]), "r"(a[1]), "r"(a[2]), "r"(a[3]), "r"(b0), "r"(b1));
}

__device__ __forceinline__ void cls_issue_loads(uint32_t sbase, int kt, int m0, int n0, int tid)
{
    const int pass = kt >> 4;
    const int k0 = (kt & 15) * 64;
    const __nv_bfloat16* Ap = (pass == 1) ? g_Ylo : g_Yhi;
    const __nv_bfloat16* Bp = (pass == 2) ? g_Wlo : g_Whi;
    const uint32_t sA = sbase + (uint32_t)(kt % CLS_STAGES) * CLS_STG_BYTES;
    const uint32_t sB = sA + 16384;
#pragma unroll
    for (int it = 0; it < 4; it++) {           // A: 128 rows x 8 chunks of 16B
        int i = it * 256 + tid;
        int row = i >> 3, q = i & 7;
        uint32_t off = (uint32_t)(row * 128 + q * 16);
        cp16(sA + swz(off), Ap + (size_t)(m0 + row) * 1024 + k0 + q * 8);
    }
#pragma unroll
    for (int it = 0; it < 4; it++) {           // B: 128 rows x 8 chunks of 16B
        int i = it * 256 + tid;
        int row = i >> 3, q = i & 7;
        uint32_t off = (uint32_t)(row * 128 + q * 16);
        cp16(sB + swz(off), Bp + (size_t)(n0 + row) * 1024 + k0 + q * 8);
    }
}

__global__ __launch_bounds__(256) void cls_tc_kernel(
    const float* __restrict__ bc, float* __restrict__ out)
{
    extern __shared__ char smc[];
    const uint32_t sbase = smem_u32(smc);
    const int tid = threadIdx.x;
    const int l   = tid & 31;
    const int w   = tid >> 5;
    const int m0c = blockIdx.x * 128;
    const int n0c = blockIdx.y * 128;
    float* biasS = (float*)(smc + OFF_CBIAS);

    if (tid < 128) biasS[tid] = bc[n0c + tid];

    const int wm = (w & 3) * 32;   // warp m base in CTA tile
    const int wn = (w >> 2) * 64;  // warp n base in CTA tile

    float acc[2][8][4];
#pragma unroll
    for (int mi = 0; mi < 2; mi++)
#pragma unroll
        for (int ni = 0; ni < 8; ni++)
#pragma unroll
            for (int q = 0; q < 4; q++) acc[mi][ni][q] = 0.0f;

    cls_issue_loads(sbase, 0, m0c, n0c, tid); cp_commit();
    cls_issue_loads(sbase, 1, m0c, n0c, tid); cp_commit();

    // precomputed intra-tile ldmatrix offsets (lane-dependent, k-chunk added in loop)
    const uint32_t aRow = (uint32_t)(((l >> 3) & 1) * 8 + (l & 7));   // + mi*16 + wm
    const uint32_t aCol = (uint32_t)((l >> 4) * 16);
    const uint32_t bRow = (uint32_t)((l >> 4) * 8 + (l & 7));         // + ng*16 + wn
    const uint32_t bCol = (uint32_t)(((l >> 3) & 1) * 16);

    for (int kt = 0; kt < CLS_NKT; kt++) {
        if (kt + 2 < CLS_NKT) {
            cls_issue_loads(sbase, kt + 2, m0c, n0c, tid);
            cp_commit();
            cp_wait<2>();
        } else if (kt + 1 < CLS_NKT) {
            cp_wait<1>();
        } else {
            cp_wait<0>();
        }
        __syncthreads();

        const uint32_t sA = sbase + (uint32_t)(kt % CLS_STAGES) * CLS_STG_BYTES;
        const uint32_t sB = sA + 16384;
#pragma unroll
        for (int ksi = 0; ksi < 4; ksi++) {
            uint32_t a[2][4];
#pragma unroll
            for (int mi = 0; mi < 2; mi++) {
                uint32_t off = (uint32_t)(wm + mi * 16 + aRow) * 128 + (uint32_t)(ksi * 32) + aCol;
                ldm_x4(sA + swz(off), a[mi][0], a[mi][1], a[mi][2], a[mi][3]);
            }
            uint32_t bf[4][4];
#pragma unroll
            for (int ng = 0; ng < 4; ng++) {
                uint32_t off = (uint32_t)(wn + ng * 16 + bRow) * 128 + (uint32_t)(ksi * 32) + bCol;
                ldm_x4(sB + swz(off), bf[ng][0], bf[ng][1], bf[ng][2], bf[ng][3]);
            }
#pragma unroll
            for (int mi = 0; mi < 2; mi++)
#pragma unroll
                for (int ng = 0; ng < 4; ng++) {
                    mma16816(acc[mi][ng * 2 + 0], a[mi], bf[ng][0], bf[ng][1]);
                    mma16816(acc[mi][ng * 2 + 1], a[mi], bf[ng][2], bf[ng][3]);
                }
        }
        __syncthreads();
    }

    // epilogue: bias + scatter into (B, T, V); C row m = t*16 + b
#pragma unroll
    for (int mi = 0; mi < 2; mi++) {
#pragma unroll
        for (int ni = 0; ni < 8; ni++) {
            int nloc = wn + ni * 8 + (l & 3) * 2;
            int n = n0c + nloc;
            float bx = biasS[nloc], by = biasS[nloc + 1];
            int m1 = m0c + wm + mi * 16 + (l >> 2);
            int m2 = m1 + 8;
            {
                int t = m1 >> 4, b = m1 & 15;
                float2 v; v.x = acc[mi][ni][0] + bx; v.y = acc[mi][ni][1] + by;
                *(float2*)&out[(size_t)b * ((size_t)TT * VV) + (size_t)t * VV + n] = v;
            }
            {
                int t = m2 >> 4, b = m2 & 15;
                float2 v; v.x = acc[mi][ni][2] + bx; v.y = acc[mi][ni][3] + by;
                *(float2*)&out[(size_t)b * ((size_t)TT * VV) + (size_t)t * VV + n] = v;
            }
        }
    }
}

// ---------------- launch ----------------
extern "C" void kernel_launch(void* const* d_in, const int* in_sizes, int n_in,
                              void* d_out, int out_size)
{
    const float* enc_h  = (const float*)d_in[0];
    const float* enc_c  = (const float*)d_in[1];
    const float* target = (const float*)d_in[2];
    const float* Wih0f = (const float*)d_in[3];
    const float* Whh0f = (const float*)d_in[4];
    const float* bi0f  = (const float*)d_in[5];
    const float* bh0f  = (const float*)d_in[6];
    const float* Wih0b = (const float*)d_in[7];
    const float* Whh0b = (const float*)d_in[8];
    const float* bi0b  = (const float*)d_in[9];
    const float* bh0b  = (const float*)d_in[10];
    const float* Wih1f = (const float*)d_in[11];
    const float* Whh1f = (const float*)d_in[12];
    const float* bi1f  = (const float*)d_in[13];
    const float* bh1f  = (const float*)d_in[14];
    const float* Wih1b = (const float*)d_in[15];
    const float* Whh1b = (const float*)d_in[16];
    const float* bi1b  = (const float*)d_in[17];
    const float* bh1b  = (const float*)d_in[18];
    const float* Wcls  = (const float*)d_in[19];
    const float* bcls  = (const float*)d_in[20];
    float* out = (float*)d_out;

    cudaFuncSetAttribute(rnn_kernel, cudaFuncAttributeMaxDynamicSharedMemorySize, SMEM_BYTES);
    cudaFuncSetAttribute(cls_tc_kernel, cudaFuncAttributeMaxDynamicSharedMemorySize, SMEM_CLS);

    // convert_w also resets the rnn barrier counters (stream-ordered before rnn)
    convert_w_kernel<<<32000, 256>>>(Wcls);           // 32000*1024 f32 -> hi/lo bf16
    rnn_kernel<<<NBLK, NTHR, SMEM_BYTES>>>(
        enc_h, enc_c, target,
        Wih0f, Whh0f, bi0f, bh0f,
        Wih0b, Whh0b, bi0b, bh0b,
        Wih1f, Whh1f, bi1f, bh1f,
        Wih1b, Whh1b, bi1b, bh1b,
        out);
    dim3 g((TT * BB) / 128, VV / 128);                // (32, 250): m fastest
    cls_tc_kernel<<<g, 256, SMEM_CLS>>>(bcls, out);
}

// round 14
// speedup vs baseline: 1.9656x; 1.5189x over previous
#include <cuda_runtime.h>
#include <cuda_bf16.h>
#include <math.h>
#include <stdint.h>

#define TT 256
#define BB 16
#define HH 512
#define VV 32000
#define NBLK 128
#define NTHR 256

// zs row stride in floats (padded 16 -> 20 to kill the 4-way LDS.128 bank conflict)
#define ZST 20
#define ZBUF (128 * ZST)            // one z buffer = 2560 floats

// ---------------- device globals (no allocations allowed) ----------------
__device__ float g_hbuf[2][4 * BB * HH];          // double-buffered h for 4 cells
__device__ float g_y0[TT * BB * 2 * HH];          // layer-0 concat outputs (fp32, rnn-internal)
__device__ unsigned g_cnt;                        // full-grid barrier counter (phase boundary)
__device__ unsigned g_cnt_half[2];                // per-chain step-barrier counters

// bf16 split buffers for tensor-core classifier
__device__ __nv_bfloat16 g_Yhi[4096 * 1024];
__device__ __nv_bfloat16 g_Ylo[4096 * 1024];
__device__ __nv_bfloat16 g_Whi[32000 * 1024];
__device__ __nv_bfloat16 g_Wlo[32000 * 1024];

// smem layout (floats) for rnn kernel
#define OFF_W     0                                // 32*1536 max = 49152
#define OFF_ZS    49152                            // 2 * ZBUF = 5120
#define OFF_GATES 54272                            // 32*16 = 512
#define OFF_BIAS  54784                            // 32
#define OFF_WIH   54816                            // 32
#define OFF_CLOC  54848                            // 128
#define SMEM_FLOATS 54976
#define SMEM_BYTES (SMEM_FLOATS * 4)               // 219,904 B

__device__ __forceinline__ float sigf(float x) {
    return __fdividef(1.0f, 1.0f + __expf(-x));
}
__device__ __forceinline__ float tanhf_fast(float x) {
    // 1 - 2/(e^{2x}+1): exact limits at +-inf, MUFU-based, rel err ~1e-7
    return 1.0f - __fdividef(2.0f, __expf(2.0f * x) + 1.0f);
}

// ---------------- persistent recurrence kernel ----------------
__global__ __launch_bounds__(NTHR, 1) void rnn_kernel(
    const float* __restrict__ enc_h,
    const float* __restrict__ enc_c,
    const float* __restrict__ target,
    const float* __restrict__ Wih0f, const float* __restrict__ Whh0f,
    const float* __restrict__ bi0f,  const float* __restrict__ bh0f,
    const float* __restrict__ Wih0b, const float* __restrict__ Whh0b,
    const float* __restrict__ bi0b,  const float* __restrict__ bh0b,
    const float* __restrict__ Wih1f, const float* __restrict__ Whh1f,
    const float* __restrict__ bi1f,  const float* __restrict__ bh1f,
    const float* __restrict__ Wih1b, const float* __restrict__ Whh1b,
    const float* __restrict__ bi1b,  const float* __restrict__ bh1b,
    float* __restrict__ out)
{
    extern __shared__ float sm[];
    float* Wsh   = sm + OFF_W;      // [32][WS]
    float* zs    = sm + OFF_ZS;     // [2][128][ZST]
    float* gates = sm + OFF_GATES;  // [32][16]
    float* biasS = sm + OFF_BIAS;   // [32]
    float* wihS  = sm + OFF_WIH;    // [32]
    float* c_loc = sm + OFF_CLOC;   // [8][16]

    const int tid  = threadIdx.x;
    const int half = blockIdx.x >> 6;        // 0: forward chain, 1: backward chain
    const int u0   = (blockIdx.x & 63) * 8;  // first hidden unit owned
    const int ks   = tid & 7;                // k-slice within warp
    const int bq   = (tid >> 3) & 3;         // batch quad
    const int rid  = tid >> 5;               // warp index = row quad
    const int sk   = tid & 127;              // staging: k within chunk
    const int bh8  = (tid >> 7) * 8;         // staging: batch half (0 or 8)

    unsigned bar_target = 0;

    for (int ph = 0; ph < 2; ph++) {
        const int K  = ph ? 1536 : 512;
        const int WS = ph ? 1536 : 512;
        const int NC = K >> 7;               // chunks of 128
        const int cell = ph * 2 + half;
        const float* Wih = ph ? (half ? Wih1b : Wih1f) : (half ? Wih0b : Wih0f);
        const float* Whh = ph ? (half ? Whh1b : Whh1f) : (half ? Whh0b : Whh0f);
        const float* bi  = ph ? (half ? bi1b  : bi1f ) : (half ? bi0b  : bi0f );
        const float* bh  = ph ? (half ? bh1b  : bh1f ) : (half ? bh0b  : bh0f );

        // ---- stage weights into smem (persist across all T steps) ----
        if (ph == 0) {
            for (int idx = tid; idx < 32 * 512; idx += NTHR) {
                int rl = idx >> 9, k = idx & 511;
                int grow = (rl >> 3) * HH + u0 + (rl & 7);
                Wsh[rl * 512 + k] = Whh[grow * HH + k];
            }
        } else {
            for (int idx = tid; idx < 32 * 1024; idx += NTHR) {
                int rl = idx >> 10, k = idx & 1023;
                int grow = (rl >> 3) * HH + u0 + (rl & 7);
                Wsh[rl * 1536 + k] = Wih[grow * 1024 + k];
            }
            for (int idx = tid; idx < 32 * 512; idx += NTHR) {
                int rl = idx >> 9, k = idx & 511;
                int grow = (rl >> 3) * HH + u0 + (rl & 7);
                Wsh[rl * 1536 + 1024 + k] = Whh[grow * HH + k];
            }
        }
        if (tid < 32) {
            int grow = (tid >> 3) * HH + u0 + (tid & 7);
            biasS[tid] = bi[grow] + bh[grow];
            if (ph == 0) wihS[tid] = Wih[grow];   // Wih_l0 is (2048,1)
        }
        if (tid < 128) {
            int j = tid >> 4, b = tid & 15;
            c_loc[tid] = enc_c[cell * BB * HH + b * HH + u0 + j];
        }
        __syncthreads();

        for (int t = 0; t < TT; t++) {
            const int p = t & 1;
            // at t==0 the previous h is the encoder state (same [cell][b][k] layout)
            const float* hsrc = (t == 0) ? enc_h : g_hbuf[p];

            float acc[4][4];
#pragma unroll
            for (int i = 0; i < 4; i++)
#pragma unroll
                for (int j = 0; j < 4; j++) acc[i][j] = 0.0f;

            float r[8];
            // ---- stage chunk 0 ----
            {
                const int kg = sk;   // kc = 0
#pragma unroll
                for (int j = 0; j < 8; j++) {
                    int b = bh8 + j;
                    float v;
                    if (ph == 0) {
                        v = __ldcg(&hsrc[cell * (BB * HH) + b * HH + kg]);
                    } else {
                        v = __ldcg(&g_y0[t * (BB * 2 * HH) + b * (2 * HH) + kg]);
                    }
                    r[j] = v;
                }
                float* zw = zs + sk * ZST + bh8;
                *(float4*)zw       = make_float4(r[0], r[1], r[2], r[3]);
                *(float4*)(zw + 4) = make_float4(r[4], r[5], r[6], r[7]);
            }
            __syncthreads();

            for (int c = 0; c < NC; c++) {
                // prefetch chunk c+1 into registers (L2 latency hidden by compute)
                if (c + 1 < NC) {
                    const int kg = (c + 1) * 128 + sk;
#pragma unroll
                    for (int j = 0; j < 8; j++) {
                        int b = bh8 + j;
                        float v;
                        if (ph == 0) {
                            v = __ldcg(&hsrc[cell * (BB * HH) + b * HH + kg]);
                        } else if (kg < 1024) {
                            v = __ldcg(&g_y0[t * (BB * 2 * HH) + b * (2 * HH) + kg]);
                        } else {
                            v = __ldcg(&hsrc[cell * (BB * HH) + b * HH + (kg - 1024)]);
                        }
                        r[j] = v;
                    }
                }

                // compute chunk c from buffer c&1 (conflict-free: ZST=20 pad)
                {
                    const float* zb = zs + (c & 1) * ZBUF;
                    const float* wp = &Wsh[(rid * 4) * WS + c * 128 + ks];
#pragma unroll
                    for (int kk = 0; kk < 128; kk += 8) {
                        float w0 = wp[0 * WS + kk];
                        float w1 = wp[1 * WS + kk];
                        float w2 = wp[2 * WS + kk];
                        float w3 = wp[3 * WS + kk];
                        const float4 z4 = *(const float4*)&zb[(kk + ks) * ZST + bq * 4];
                        acc[0][0] += w0 * z4.x; acc[0][1] += w0 * z4.y; acc[0][2] += w0 * z4.z; acc[0][3] += w0 * z4.w;
                        acc[1][0] += w1 * z4.x; acc[1][1] += w1 * z4.y; acc[1][2] += w1 * z4.z; acc[1][3] += w1 * z4.w;
                        acc[2][0] += w2 * z4.x; acc[2][1] += w2 * z4.y; acc[2][2] += w2 * z4.z; acc[2][3] += w2 * z4.w;
                        acc[3][0] += w3 * z4.x; acc[3][1] += w3 * z4.y; acc[3][2] += w3 * z4.z; acc[3][3] += w3 * z4.w;
                    }
                }

                if (c + 1 < NC) {
                    float* zw = zs + ((c + 1) & 1) * ZBUF + sk * ZST + bh8;
                    *(float4*)zw       = make_float4(r[0], r[1], r[2], r[3]);
                    *(float4*)(zw + 4) = make_float4(r[4], r[5], r[6], r[7]);
                }
                __syncthreads();
            }

            // reduce the 8-way k-split inside each warp (ks lives in lane bits 0-2)
#pragma unroll
            for (int i = 0; i < 4; i++)
#pragma unroll
                for (int j = 0; j < 4; j++) {
                    float v = acc[i][j];
                    v += __shfl_xor_sync(0xffffffffu, v, 1);
                    v += __shfl_xor_sync(0xffffffffu, v, 2);
                    v += __shfl_xor_sync(0xffffffffu, v, 4);
                    if (ks == 0) gates[(rid * 4 + i) * 16 + (bq * 4 + j)] = v;
                }
            __syncthreads();

            if (tid < 128) {
                int j = tid >> 4, b = tid & 15;
                float gi = gates[(0  + j) * 16 + b] + biasS[j];
                float gf = gates[(8  + j) * 16 + b] + biasS[8 + j];
                float gg = gates[(16 + j) * 16 + b] + biasS[16 + j];
                float go = gates[(24 + j) * 16 + b] + biasS[24 + j];
                if (ph == 0) {
                    float x = target[b * TT + t];
                    gi += x * wihS[j];
                    gf += x * wihS[8 + j];
                    gg += x * wihS[16 + j];
                    go += x * wihS[24 + j];
                }
                float cprev = c_loc[tid];
                float cn = sigf(gf) * cprev + sigf(gi) * tanhf_fast(gg);
                float hn = sigf(go) * tanhf_fast(cn);
                c_loc[tid] = cn;
                int u = u0 + j;
                g_hbuf[p ^ 1][cell * (BB * HH) + b * HH + u] = hn;
                if (ph == 0) {
                    g_y0[t * (BB * 2 * HH) + b * (2 * HH) + half * HH + u] = hn;
                } else {
                    // fused bf16 hi/lo split of y1 for the classifier
                    __nv_bfloat16 hh = __float2bfloat16(hn);
                    __nv_bfloat16 hl = __float2bfloat16(hn - __bfloat162float(hh));
                    size_t yi = (size_t)(t * 16 + b) * 1024 + (size_t)(half * HH + u);
                    g_Yhi[yi] = hh;
                    g_Ylo[yi] = hl;
                }
                if (t == TT - 1) {
                    long hoff = (long)BB * TT * VV;
                    out[hoff + cell * (BB * HH) + b * HH + u] = hn;
                    out[hoff + 4 * BB * HH + cell * (BB * HH) + b * HH + u] = cn;
                }
            }

            // ---- throttled counter barrier across the 64 blocks of this chain ----
            __syncthreads();
            bar_target += 64;
            if (tid == 0) {
                __threadfence();
                atomicAdd(&g_cnt_half[half], 1u);
                while (*((volatile unsigned*)&g_cnt_half[half]) < bar_target) __nanosleep(32);
            }
            __syncthreads();
        }

        // ---- full-grid barrier at phase boundary (y0 must be complete) ----
        if (ph == 0) {
            if (tid == 0) {
                __threadfence();
                atomicAdd(&g_cnt, 1u);
                while (*((volatile unsigned*)&g_cnt) < NBLK) __nanosleep(64);
            }
            __syncthreads();
        }
    }
}

// ================= bf16 split conversion (weights) + barrier-counter reset =================
__device__ __forceinline__ void split2(float x, __nv_bfloat16& h, __nv_bfloat16& l) {
    h = __float2bfloat16(x);
    l = __float2bfloat16(x - __bfloat162float(h));
}

__global__ void convert_w_kernel(const float* __restrict__ W) {
    if (blockIdx.x == 0 && threadIdx.x == 0) {
        g_cnt = 0u;
        g_cnt_half[0] = 0u;
        g_cnt_half[1] = 0u;
    }
    size_t i = (size_t)blockIdx.x * 256 + threadIdx.x;   // quad index
    size_t base = i * 4;
    float4 v = *(const float4*)(W + base);
    __nv_bfloat16 h0, h1, h2, h3, l0, l1, l2, l3;
    split2(v.x, h0, l0); split2(v.y, h1, l1);
    split2(v.z, h2, l2); split2(v.w, h3, l3);
    ushort4 hs, ls;
    hs.x = __bfloat16_as_ushort(h0); hs.y = __bfloat16_as_ushort(h1);
    hs.z = __bfloat16_as_ushort(h2); hs.w = __bfloat16_as_ushort(h3);
    ls.x = __bfloat16_as_ushort(l0); ls.y = __bfloat16_as_ushort(l1);
    ls.z = __bfloat16_as_ushort(l2); ls.w = __bfloat16_as_ushort(l3);
    *(ushort4*)(g_Whi + base) = hs;
    *(ushort4*)(g_Wlo + base) = ls;
}

// ================= mma.sync bf16 classifier GEMM (R10 proven config) =================
// C[4096, 32000] = Yhi*Whi^T + Ylo*Whi^T + Yhi*Wlo^T  (48 K-tiles of 64 = 3 x 1024)
// CTA tile 128x128, BK=64 bf16 (128B rows, SW128 swizzle), 3-stage cp.async pipeline.
// 8 warps = 4(m) x 2(n); warp tile 32x64; 98KB smem -> 2 CTAs/SM.
// Raster: blockIdx.x = m (32), blockIdx.y = n (250): wave shares each W tile in L2.

#define CLS_NKT 48
#define CLS_STG_BYTES 32768        // A 16KB + B 16KB
#define CLS_STAGES 3
#define OFF_CBIAS (CLS_STAGES * CLS_STG_BYTES)       // 98304
#define SMEM_CLS  (OFF_CBIAS + 128 * 4)

__device__ __forceinline__ uint32_t smem_u32(const void* p) {
    uint32_t a;
    asm("{ .reg .u64 t; cvta.to.shared.u64 t, %1; cvt.u32.u64 %0, t; }" : "=r"(a) : "l"(p));
    return a;
}
__device__ __forceinline__ uint32_t swz(uint32_t off) {
    return off ^ ((off >> 3) & 0x70);
}
__device__ __forceinline__ void cp16(uint32_t saddr, const void* g) {
    asm volatile("cp.async.cg.shared.global [%0], [%1], 16;" :: "r"(saddr), "l"(g));
}
__device__ __forceinline__ void cp_commit() { asm volatile("cp.async.commit_group;" ::: "memory"); }
template <int N> __device__ __forceinline__ void cp_wait() {
    asm volatile("cp.async.wait_group %0;" :: "n"(N) : "memory");
}
__device__ __forceinline__ void ldm_x4(uint32_t addr, uint32_t& r0, uint32_t& r1,
                                       uint32_t& r2, uint32_t& r3) {
    asm volatile("ldmatrix.sync.aligned.m8n8.x4.shared.b16 {%0,%1,%2,%3}, [%4];"
                 : "=r"(r0), "=r"(r1), "=r"(r2), "=r"(r3) : "r"(addr));
}
__device__ __forceinline__ void mma16816(float* d, const uint32_t* a, uint32_t b0, uint32_t b1) {
    asm volatile(
        "mma.sync.aligned.m16n8k16.row.col.f32.bf16.bf16.f32 "
        "{%0,%1,%2,%3}, {%4,%5,%6,%7}, {%8,%9}, {%0,%1,%2,%3};"
        : "+f"(d[0]), "+f"(d[1]), "+f"(d[2]), "+f"(d[3])
        : "r"(a[0]), "r"(a[1]), "r"(a[2]), "r"(a[3]), "r"(b0), "r"(b1));
}

__device__ __forceinline__ void cls_issue_loads(uint32_t sbase, int kt, int m0, int n0, int tid)
{
    const int pass = kt >> 4;
    const int k0 = (kt & 15) * 64;
    const __nv_bfloat16* Ap = (pass == 1) ? g_Ylo : g_Yhi;
    const __nv_bfloat16* Bp = (pass == 2) ? g_Wlo : g_Whi;
    const uint32_t sA = sbase + (uint32_t)(kt % CLS_STAGES) * CLS_STG_BYTES;
    const uint32_t sB = sA + 16384;
#pragma unroll
    for (int it = 0; it < 4; it++) {           // A: 128 rows x 8 chunks of 16B
        int i = it * 256 + tid;
        int row = i >> 3, q = i & 7;
        uint32_t off = (uint32_t)(row * 128 + q * 16);
        cp16(sA + swz(off), Ap + (size_t)(m0 + row) * 1024 + k0 + q * 8);
    }
#pragma unroll
    for (int it = 0; it < 4; it++) {           // B: 128 rows x 8 chunks of 16B
        int i = it * 256 + tid;
        int row = i >> 3, q = i & 7;
        uint32_t off = (uint32_t)(row * 128 + q * 16);
        cp16(sB + swz(off), Bp + (size_t)(n0 + row) * 1024 + k0 + q * 8);
    }
}

__global__ __launch_bounds__(256) void cls_tc_kernel(
    const float* __restrict__ bc, float* __restrict__ out)
{
    extern __shared__ char smc[];
    const uint32_t sbase = smem_u32(smc);
    const int tid = threadIdx.x;
    const int l   = tid & 31;
    const int w   = tid >> 5;
    const int m0c = blockIdx.x * 128;
    const int n0c = blockIdx.y * 128;
    float* biasS = (float*)(smc + OFF_CBIAS);

    if (tid < 128) biasS[tid] = bc[n0c + tid];

    const int wm = (w & 3) * 32;   // warp m base in CTA tile
    const int wn = (w >> 2) * 64;  // warp n base in CTA tile

    float acc[2][8][4];
#pragma unroll
    for (int mi = 0; mi < 2; mi++)
#pragma unroll
        for (int ni = 0; ni < 8; ni++)
#pragma unroll
            for (int q = 0; q < 4; q++) acc[mi][ni][q] = 0.0f;

    cls_issue_loads(sbase, 0, m0c, n0c, tid); cp_commit();
    cls_issue_loads(sbase, 1, m0c, n0c, tid); cp_commit();

    // precomputed intra-tile ldmatrix offsets (lane-dependent, k-chunk added in loop)
    const uint32_t aRow = (uint32_t)(((l >> 3) & 1) * 8 + (l & 7));   // + mi*16 + wm
    const uint32_t aCol = (uint32_t)((l >> 4) * 16);
    const uint32_t bRow = (uint32_t)((l >> 4) * 8 + (l & 7));         // + ng*16 + wn
    const uint32_t bCol = (uint32_t)(((l >> 3) & 1) * 16);

    for (int kt = 0; kt < CLS_NKT; kt++) {
        if (kt + 2 < CLS_NKT) {
            cls_issue_loads(sbase, kt + 2, m0c, n0c, tid);
            cp_commit();
            cp_wait<2>();
        } else if (kt + 1 < CLS_NKT) {
            cp_wait<1>();
        } else {
            cp_wait<0>();
        }
        __syncthreads();

        const uint32_t sA = sbase + (uint32_t)(kt % CLS_STAGES) * CLS_STG_BYTES;
        const uint32_t sB = sA + 16384;
#pragma unroll
        for (int ksi = 0; ksi < 4; ksi++) {
            uint32_t a[2][4];
#pragma unroll
            for (int mi = 0; mi < 2; mi++) {
                uint32_t off = (uint32_t)(wm + mi * 16 + aRow) * 128 + (uint32_t)(ksi * 32) + aCol;
                ldm_x4(sA + swz(off), a[mi][0], a[mi][1], a[mi][2], a[mi][3]);
            }
            uint32_t bf[4][4];
#pragma unroll
            for (int ng = 0; ng < 4; ng++) {
                uint32_t off = (uint32_t)(wn + ng * 16 + bRow) * 128 + (uint32_t)(ksi * 32) + bCol;
                ldm_x4(sB + swz(off), bf[ng][0], bf[ng][1], bf[ng][2], bf[ng][3]);
            }
#pragma unroll
            for (int mi = 0; mi < 2; mi++)
#pragma unroll
                for (int ng = 0; ng < 4; ng++) {
                    mma16816(acc[mi][ng * 2 + 0], a[mi], bf[ng][0], bf[ng][1]);
                    mma16816(acc[mi][ng * 2 + 1], a[mi], bf[ng][2], bf[ng][3]);
                }
        }
        __syncthreads();
    }

    // epilogue: bias + scatter into (B, T, V); C row m = t*16 + b
#pragma unroll
    for (int mi = 0; mi < 2; mi++) {
#pragma unroll
        for (int ni = 0; ni < 8; ni++) {
            int nloc = wn + ni * 8 + (l & 3) * 2;
            int n = n0c + nloc;
            float bx = biasS[nloc], by = biasS[nloc + 1];
            int m1 = m0c + wm + mi * 16 + (l >> 2);
            int m2 = m1 + 8;
            {
                int t = m1 >> 4, b = m1 & 15;
                float2 v; v.x = acc[mi][ni][0] + bx; v.y = acc[mi][ni][1] + by;
                *(float2*)&out[(size_t)b * ((size_t)TT * VV) + (size_t)t * VV + n] = v;
            }
            {
                int t = m2 >> 4, b = m2 & 15;
                float2 v; v.x = acc[mi][ni][2] + bx; v.y = acc[mi][ni][3] + by;
                *(float2*)&out[(size_t)b * ((size_t)TT * VV) + (size_t)t * VV + n] = v;
            }
        }
    }
}

// ---------------- launch ----------------
extern "C" void kernel_launch(void* const* d_in, const int* in_sizes, int n_in,
                              void* d_out, int out_size)
{
    const float* enc_h  = (const float*)d_in[0];
    const float* enc_c  = (const float*)d_in[1];
    const float* target = (const float*)d_in[2];
    const float* Wih0f = (const float*)d_in[3];
    const float* Whh0f = (const float*)d_in[4];
    const float* bi0f  = (const float*)d_in[5];
    const float* bh0f  = (const float*)d_in[6];
    const float* Wih0b = (const float*)d_in[7];
    const float* Whh0b = (const float*)d_in[8];
    const float* bi0b  = (const float*)d_in[9];
    const float* bh0b  = (const float*)d_in[10];
    const float* Wih1f = (const float*)d_in[11];
    const float* Whh1f = (const float*)d_in[12];
    const float* bi1f  = (const float*)d_in[13];
    const float* bh1f  = (const float*)d_in[14];
    const float* Wih1b = (const float*)d_in[15];
    const float* Whh1b = (const float*)d_in[16];
    const float* bi1b  = (const float*)d_in[17];
    const float* bh1b  = (const float*)d_in[18];
    const float* Wcls  = (const float*)d_in[19];
    const float* bcls  = (const float*)d_in[20];
    float* out = (float*)d_out;

    cudaFuncSetAttribute(rnn_kernel, cudaFuncAttributeMaxDynamicSharedMemorySize, SMEM_BYTES);
    cudaFuncSetAttribute(cls_tc_kernel, cudaFuncAttributeMaxDynamicSharedMemorySize, SMEM_CLS);

    // convert_w also resets the rnn barrier counters (stream-ordered before rnn)
    convert_w_kernel<<<32000, 256>>>(Wcls);           // 32000*1024 f32 -> hi/lo bf16
    rnn_kernel<<<NBLK, NTHR, SMEM_BYTES>>>(
        enc_h, enc_c, target,
        Wih0f, Whh0f, bi0f, bh0f,
        Wih0b, Whh0b, bi0b, bh0b,
        Wih1f, Whh1f, bi1f, bh1f,
        Wih1b, Whh1b, bi1b, bh1b,
        out);
    dim3 g((TT * BB) / 128, VV / 128);                // (32, 250): m fastest
    cls_tc_kernel<<<g, 256, SMEM_CLS>>>(bcls, out);
}

// round 15
// speedup vs baseline: 1.9829x; 1.0088x over previous
#include <cuda_runtime.h>
#include <cuda_bf16.h>
#include <math.h>
#include <stdint.h>

#define TT 256
#define BB 16
#define HH 512
#define VV 32000
#define NBLK 128
#define NTHR 256

// zs row stride in floats (padded 16 -> 20 to kill the 4-way LDS.128 bank conflict)
#define ZST 20
#define ZBUF (128 * ZST)            // one z buffer = 2560 floats

// ---------------- device globals (no allocations allowed) ----------------
__device__ float g_hbuf[2][4 * BB * HH];          // double-buffered h for 4 cells
__device__ float g_y0[TT * BB * 2 * HH];          // layer-0 concat outputs (fp32, rnn-internal)
__device__ unsigned g_cnt;                        // full-grid barrier counter (phase boundary)
__device__ unsigned g_cnt_half[2];                // per-chain step-barrier counters

// bf16 split buffers for tensor-core classifier
__device__ __nv_bfloat16 g_Yhi[4096 * 1024];
__device__ __nv_bfloat16 g_Ylo[4096 * 1024];
__device__ __nv_bfloat16 g_Whi[32000 * 1024];
__device__ __nv_bfloat16 g_Wlo[32000 * 1024];

// smem layout (floats) for rnn kernel
#define OFF_W     0                                // 32*1536 max = 49152
#define OFF_ZS    49152                            // 2 * ZBUF = 5120
#define OFF_GATES 54272                            // 32*16 = 512
#define OFF_BIAS  54784                            // 32
#define OFF_WIH   54816                            // 32
#define OFF_CLOC  54848                            // 128
#define SMEM_FLOATS 54976
#define SMEM_BYTES (SMEM_FLOATS * 4)               // 219,904 B

__device__ __forceinline__ float sigf(float x) {
    return __fdividef(1.0f, 1.0f + __expf(-x));
}
__device__ __forceinline__ float tanhf_fast(float x) {
    // 1 - 2/(e^{2x}+1): exact limits at +-inf, MUFU-based, rel err ~1e-7
    return 1.0f - __fdividef(2.0f, __expf(2.0f * x) + 1.0f);
}

// ---------------- persistent recurrence kernel (R14 proven, unchanged) ----------------
__global__ __launch_bounds__(NTHR, 1) void rnn_kernel(
    const float* __restrict__ enc_h,
    const float* __restrict__ enc_c,
    const float* __restrict__ target,
    const float* __restrict__ Wih0f, const float* __restrict__ Whh0f,
    const float* __restrict__ bi0f,  const float* __restrict__ bh0f,
    const float* __restrict__ Wih0b, const float* __restrict__ Whh0b,
    const float* __restrict__ bi0b,  const float* __restrict__ bh0b,
    const float* __restrict__ Wih1f, const float* __restrict__ Whh1f,
    const float* __restrict__ bi1f,  const float* __restrict__ bh1f,
    const float* __restrict__ Wih1b, const float* __restrict__ Whh1b,
    const float* __restrict__ bi1b,  const float* __restrict__ bh1b,
    float* __restrict__ out)
{
    extern __shared__ float sm[];
    float* Wsh   = sm + OFF_W;      // [32][WS]
    float* zs    = sm + OFF_ZS;     // [2][128][ZST]
    float* gates = sm + OFF_GATES;  // [32][16]
    float* biasS = sm + OFF_BIAS;   // [32]
    float* wihS  = sm + OFF_WIH;    // [32]
    float* c_loc = sm + OFF_CLOC;   // [8][16]

    const int tid  = threadIdx.x;
    const int half = blockIdx.x >> 6;        // 0: forward chain, 1: backward chain
    const int u0   = (blockIdx.x & 63) * 8;  // first hidden unit owned
    const int ks   = tid & 7;                // k-slice within warp
    const int bq   = (tid >> 3) & 3;         // batch quad
    const int rid  = tid >> 5;               // warp index = row quad
    const int sk   = tid & 127;              // staging: k within chunk
    const int bh8  = (tid >> 7) * 8;         // staging: batch half (0 or 8)

    unsigned bar_target = 0;

    for (int ph = 0; ph < 2; ph++) {
        const int K  = ph ? 1536 : 512;
        const int WS = ph ? 1536 : 512;
        const int NC = K >> 7;               // chunks of 128
        const int cell = ph * 2 + half;
        const float* Wih = ph ? (half ? Wih1b : Wih1f) : (half ? Wih0b : Wih0f);
        const float* Whh = ph ? (half ? Whh1b : Whh1f) : (half ? Whh0b : Whh0f);
        const float* bi  = ph ? (half ? bi1b  : bi1f ) : (half ? bi0b  : bi0f );
        const float* bh  = ph ? (half ? bh1b  : bh1f ) : (half ? bh0b  : bh0f );

        // ---- stage weights into smem (persist across all T steps) ----
        if (ph == 0) {
            for (int idx = tid; idx < 32 * 512; idx += NTHR) {
                int rl = idx >> 9, k = idx & 511;
                int grow = (rl >> 3) * HH + u0 + (rl & 7);
                Wsh[rl * 512 + k] = Whh[grow * HH + k];
            }
        } else {
            for (int idx = tid; idx < 32 * 1024; idx += NTHR) {
                int rl = idx >> 10, k = idx & 1023;
                int grow = (rl >> 3) * HH + u0 + (rl & 7);
                Wsh[rl * 1536 + k] = Wih[grow * 1024 + k];
            }
            for (int idx = tid; idx < 32 * 512; idx += NTHR) {
                int rl = idx >> 9, k = idx & 511;
                int grow = (rl >> 3) * HH + u0 + (rl & 7);
                Wsh[rl * 1536 + 1024 + k] = Whh[grow * HH + k];
            }
        }
        if (tid < 32) {
            int grow = (tid >> 3) * HH + u0 + (tid & 7);
            biasS[tid] = bi[grow] + bh[grow];
            if (ph == 0) wihS[tid] = Wih[grow];   // Wih_l0 is (2048,1)
        }
        if (tid < 128) {
            int j = tid >> 4, b = tid & 15;
            c_loc[tid] = enc_c[cell * BB * HH + b * HH + u0 + j];
        }
        __syncthreads();

        for (int t = 0; t < TT; t++) {
            const int p = t & 1;
            // at t==0 the previous h is the encoder state (same [cell][b][k] layout)
            const float* hsrc = (t == 0) ? enc_h : g_hbuf[p];

            float acc[4][4];
#pragma unroll
            for (int i = 0; i < 4; i++)
#pragma unroll
                for (int j = 0; j < 4; j++) acc[i][j] = 0.0f;

            float r[8];
            // ---- stage chunk 0 ----
            {
                const int kg = sk;   // kc = 0
#pragma unroll
                for (int j = 0; j < 8; j++) {
                    int b = bh8 + j;
                    float v;
                    if (ph == 0) {
                        v = __ldcg(&hsrc[cell * (BB * HH) + b * HH + kg]);
                    } else {
                        v = __ldcg(&g_y0[t * (BB * 2 * HH) + b * (2 * HH) + kg]);
                    }
                    r[j] = v;
                }
                float* zw = zs + sk * ZST + bh8;
                *(float4*)zw       = make_float4(r[0], r[1], r[2], r[3]);
                *(float4*)(zw + 4) = make_float4(r[4], r[5], r[6], r[7]);
            }
            __syncthreads();

            for (int c = 0; c < NC; c++) {
                // prefetch chunk c+1 into registers (L2 latency hidden by compute)
                if (c + 1 < NC) {
                    const int kg = (c + 1) * 128 + sk;
#pragma unroll
                    for (int j = 0; j < 8; j++) {
                        int b = bh8 + j;
                        float v;
                        if (ph == 0) {
                            v = __ldcg(&hsrc[cell * (BB * HH) + b * HH + kg]);
                        } else if (kg < 1024) {
                            v = __ldcg(&g_y0[t * (BB * 2 * HH) + b * (2 * HH) + kg]);
                        } else {
                            v = __ldcg(&hsrc[cell * (BB * HH) + b * HH + (kg - 1024)]);
                        }
                        r[j] = v;
                    }
                }

                // compute chunk c from buffer c&1 (conflict-free: ZST=20 pad)
                {
                    const float* zb = zs + (c & 1) * ZBUF;
                    const float* wp = &Wsh[(rid * 4) * WS + c * 128 + ks];
#pragma unroll
                    for (int kk = 0; kk < 128; kk += 8) {
                        float w0 = wp[0 * WS + kk];
                        float w1 = wp[1 * WS + kk];
                        float w2 = wp[2 * WS + kk];
                        float w3 = wp[3 * WS + kk];
                        const float4 z4 = *(const float4*)&zb[(kk + ks) * ZST + bq * 4];
                        acc[0][0] += w0 * z4.x; acc[0][1] += w0 * z4.y; acc[0][2] += w0 * z4.z; acc[0][3] += w0 * z4.w;
                        acc[1][0] += w1 * z4.x; acc[1][1] += w1 * z4.y; acc[1][2] += w1 * z4.z; acc[1][3] += w1 * z4.w;
                        acc[2][0] += w2 * z4.x; acc[2][1] += w2 * z4.y; acc[2][2] += w2 * z4.z; acc[2][3] += w2 * z4.w;
                        acc[3][0] += w3 * z4.x; acc[3][1] += w3 * z4.y; acc[3][2] += w3 * z4.z; acc[3][3] += w3 * z4.w;
                    }
                }

                if (c + 1 < NC) {
                    float* zw = zs + ((c + 1) & 1) * ZBUF + sk * ZST + bh8;
                    *(float4*)zw       = make_float4(r[0], r[1], r[2], r[3]);
                    *(float4*)(zw + 4) = make_float4(r[4], r[5], r[6], r[7]);
                }
                __syncthreads();
            }

            // reduce the 8-way k-split inside each warp (ks lives in lane bits 0-2)
#pragma unroll
            for (int i = 0; i < 4; i++)
#pragma unroll
                for (int j = 0; j < 4; j++) {
                    float v = acc[i][j];
                    v += __shfl_xor_sync(0xffffffffu, v, 1);
                    v += __shfl_xor_sync(0xffffffffu, v, 2);
                    v += __shfl_xor_sync(0xffffffffu, v, 4);
                    if (ks == 0) gates[(rid * 4 + i) * 16 + (bq * 4 + j)] = v;
                }
            __syncthreads();

            if (tid < 128) {
                int j = tid >> 4, b = tid & 15;
                float gi = gates[(0  + j) * 16 + b] + biasS[j];
                float gf = gates[(8  + j) * 16 + b] + biasS[8 + j];
                float gg = gates[(16 + j) * 16 + b] + biasS[16 + j];
                float go = gates[(24 + j) * 16 + b] + biasS[24 + j];
                if (ph == 0) {
                    float x = target[b * TT + t];
                    gi += x * wihS[j];
                    gf += x * wihS[8 + j];
                    gg += x * wihS[16 + j];
                    go += x * wihS[24 + j];
                }
                float cprev = c_loc[tid];
                float cn = sigf(gf) * cprev + sigf(gi) * tanhf_fast(gg);
                float hn = sigf(go) * tanhf_fast(cn);
                c_loc[tid] = cn;
                int u = u0 + j;
                g_hbuf[p ^ 1][cell * (BB * HH) + b * HH + u] = hn;
                if (ph == 0) {
                    g_y0[t * (BB * 2 * HH) + b * (2 * HH) + half * HH + u] = hn;
                } else {
                    // fused bf16 hi/lo split of y1 for the classifier
                    __nv_bfloat16 hh = __float2bfloat16(hn);
                    __nv_bfloat16 hl = __float2bfloat16(hn - __bfloat162float(hh));
                    size_t yi = (size_t)(t * 16 + b) * 1024 + (size_t)(half * HH + u);
                    g_Yhi[yi] = hh;
                    g_Ylo[yi] = hl;
                }
                if (t == TT - 1) {
                    long hoff = (long)BB * TT * VV;
                    out[hoff + cell * (BB * HH) + b * HH + u] = hn;
                    out[hoff + 4 * BB * HH + cell * (BB * HH) + b * HH + u] = cn;
                }
            }

            // ---- throttled counter barrier across the 64 blocks of this chain ----
            __syncthreads();
            bar_target += 64;
            if (tid == 0) {
                __threadfence();
                atomicAdd(&g_cnt_half[half], 1u);
                while (*((volatile unsigned*)&g_cnt_half[half]) < bar_target) __nanosleep(32);
            }
            __syncthreads();
        }

        // ---- full-grid barrier at phase boundary (y0 must be complete) ----
        if (ph == 0) {
            if (tid == 0) {
                __threadfence();
                atomicAdd(&g_cnt, 1u);
                while (*((volatile unsigned*)&g_cnt) < NBLK) __nanosleep(64);
            }
            __syncthreads();
        }
    }
}

// ================= bf16 split conversion (weights) + barrier-counter reset =================
__device__ __forceinline__ void split2(float x, __nv_bfloat16& h, __nv_bfloat16& l) {
    h = __float2bfloat16(x);
    l = __float2bfloat16(x - __bfloat162float(h));
}

__global__ void convert_w_kernel(const float* __restrict__ W) {
    if (blockIdx.x == 0 && threadIdx.x == 0) {
        g_cnt = 0u;
        g_cnt_half[0] = 0u;
        g_cnt_half[1] = 0u;
    }
    size_t i = (size_t)blockIdx.x * 256 + threadIdx.x;   // quad index
    size_t base = i * 4;
    float4 v = *(const float4*)(W + base);
    __nv_bfloat16 h0, h1, h2, h3, l0, l1, l2, l3;
    split2(v.x, h0, l0); split2(v.y, h1, l1);
    split2(v.z, h2, l2); split2(v.w, h3, l3);
    ushort4 hs, ls;
    hs.x = __bfloat16_as_ushort(h0); hs.y = __bfloat16_as_ushort(h1);
    hs.z = __bfloat16_as_ushort(h2); hs.w = __bfloat16_as_ushort(h3);
    ls.x = __bfloat16_as_ushort(l0); ls.y = __bfloat16_as_ushort(l1);
    ls.z = __bfloat16_as_ushort(l2); ls.w = __bfloat16_as_ushort(l3);
    *(ushort4*)(g_Whi + base) = hs;
    *(ushort4*)(g_Wlo + base) = ls;
}

// ================= mma.sync bf16 classifier GEMM =================
// C = Yhi*Whi^T + Ylo*Whi^T + Yhi*Wlo^T, with passes 1+2 FUSED (Whi B-tile shared):
//   kt 0..15  (dual):  stage {Ahi, Alo, Bhi};  acc += Ahi*Bhi + Alo*Bhi
//   kt 16..31 (single): stage {Ahi, Blo};      acc += Ahi*Blo
// CTA tile 128x128, BK=64 (SW128), 2-stage x 48KB pipeline -> 96.5KB smem, 2 CTAs/SM.
// 8 warps = 4(m) x 2(n); warp tile 32x64; A-fragment registers reused hi->lo.

#define CLS_NKT 32
#define CLS_STG_BYTES 49152        // Ahi 16KB + Alo 16KB + B 16KB
#define CLS_STAGES 2
#define OFF_CBIAS (CLS_STAGES * CLS_STG_BYTES)       // 98304
#define SMEM_CLS  (OFF_CBIAS + 128 * 4)              // 98816

__device__ __forceinline__ uint32_t smem_u32(const void* p) {
    uint32_t a;
    asm("{ .reg .u64 t; cvta.to.shared.u64 t, %1; cvt.u32.u64 %0, t; }" : "=r"(a) : "l"(p));
    return a;
}
__device__ __forceinline__ uint32_t swz(uint32_t off) {
    return off ^ ((off >> 3) & 0x70);
}
__device__ __forceinline__ void cp16(uint32_t saddr, const void* g) {
    asm volatile("cp.async.cg.shared.global [%0], [%1], 16;" :: "r"(saddr), "l"(g));
}
__device__ __forceinline__ void cp_commit() { asm volatile("cp.async.commit_group;" ::: "memory"); }
template <int N> __device__ __forceinline__ void cp_wait() {
    asm volatile("cp.async.wait_group %0;" :: "n"(N) : "memory");
}
__device__ __forceinline__ void ldm_x4(uint32_t addr, uint32_t& r0, uint32_t& r1,
                                       uint32_t& r2, uint32_t& r3) {
    asm volatile("ldmatrix.sync.aligned.m8n8.x4.shared.b16 {%0,%1,%2,%3}, [%4];"
                 : "=r"(r0), "=r"(r1), "=r"(r2), "=r"(r3) : "r"(addr));
}
__device__ __forceinline__ void mma16816(float* d, const uint32_t* a, uint32_t b0, uint32_t b1) {
    asm volatile(
        "mma.sync.aligned.m16n8k16.row.col.f32.bf16.bf16.f32 "
        "{%0,%1,%2,%3}, {%4,%5,%6,%7}, {%8,%9}, {%0,%1,%2,%3};"
        : "+f"(d[0]), "+f"(d[1]), "+f"(d[2]), "+f"(d[3])
        : "r"(a[0]), "r"(a[1]), "r"(a[2]), "r"(a[3]), "r"(b0), "r"(b1));
}

__device__ __forceinline__ void cls_issue_loads(uint32_t sbase, int kt, int m0, int n0, int tid)
{
    const int dual = (kt < 16);
    const int k0 = (kt & 15) * 64;
    const __nv_bfloat16* Bp = dual ? g_Whi : g_Wlo;
    const uint32_t sS = sbase + (uint32_t)(kt & 1) * CLS_STG_BYTES;
#pragma unroll
    for (int it = 0; it < 4; it++) {           // Ahi: 128 rows x 8 chunks of 16B
        int i = it * 256 + tid;
        int row = i >> 3, q = i & 7;
        uint32_t off = (uint32_t)(row * 128 + q * 16);
        cp16(sS + swz(off), g_Yhi + (size_t)(m0 + row) * 1024 + k0 + q * 8);
    }
    if (dual) {
#pragma unroll
        for (int it = 0; it < 4; it++) {       // Alo
            int i = it * 256 + tid;
            int row = i >> 3, q = i & 7;
            uint32_t off = (uint32_t)(row * 128 + q * 16);
            cp16(sS + 16384 + swz(off), g_Ylo + (size_t)(m0 + row) * 1024 + k0 + q * 8);
        }
    }
#pragma unroll
    for (int it = 0; it < 4; it++) {           // B: 128 rows x 8 chunks of 16B
        int i = it * 256 + tid;
        int row = i >> 3, q = i & 7;
        uint32_t off = (uint32_t)(row * 128 + q * 16);
        cp16(sS + 32768 + swz(off), Bp + (size_t)(n0 + row) * 1024 + k0 + q * 8);
    }
}

__global__ __launch_bounds__(256) void cls_tc_kernel(
    const float* __restrict__ bc, float* __restrict__ out)
{
    extern __shared__ char smc[];
    const uint32_t sbase = smem_u32(smc);
    const int tid = threadIdx.x;
    const int l   = tid & 31;
    const int w   = tid >> 5;
    const int m0c = blockIdx.x * 128;
    const int n0c = blockIdx.y * 128;
    float* biasS = (float*)(smc + OFF_CBIAS);

    if (tid < 128) biasS[tid] = bc[n0c + tid];

    const int wm = (w & 3) * 32;   // warp m base in CTA tile
    const int wn = (w >> 2) * 64;  // warp n base in CTA tile

    float acc[2][8][4];
#pragma unroll
    for (int mi = 0; mi < 2; mi++)
#pragma unroll
        for (int ni = 0; ni < 8; ni++)
#pragma unroll
            for (int q = 0; q < 4; q++) acc[mi][ni][q] = 0.0f;

    cls_issue_loads(sbase, 0, m0c, n0c, tid); cp_commit();
    cls_issue_loads(sbase, 1, m0c, n0c, tid); cp_commit();

    // precomputed intra-tile ldmatrix offsets (lane-dependent, k-chunk added in loop)
    const uint32_t aRow = (uint32_t)(((l >> 3) & 1) * 8 + (l & 7));   // + mi*16 + wm
    const uint32_t aCol = (uint32_t)((l >> 4) * 16);
    const uint32_t bRow = (uint32_t)((l >> 4) * 8 + (l & 7));         // + ng*16 + wn
    const uint32_t bCol = (uint32_t)(((l >> 3) & 1) * 16);

    for (int kt = 0; kt < CLS_NKT; kt++) {
        if (kt + 1 < CLS_NKT) cp_wait<1>(); else cp_wait<0>();
        __syncthreads();

        const int dual = (kt < 16);
        const uint32_t sS = sbase + (uint32_t)(kt & 1) * CLS_STG_BYTES;
        const uint32_t sB = sS + 32768;
#pragma unroll
        for (int ksi = 0; ksi < 4; ksi++) {
            uint32_t bf[4][4];
#pragma unroll
            for (int ng = 0; ng < 4; ng++) {
                uint32_t off = (uint32_t)(wn + ng * 16 + bRow) * 128 + (uint32_t)(ksi * 32) + bCol;
                ldm_x4(sB + swz(off), bf[ng][0], bf[ng][1], bf[ng][2], bf[ng][3]);
            }
            uint32_t a[2][4];
            // --- hi A ---
#pragma unroll
            for (int mi = 0; mi < 2; mi++) {
                uint32_t off = (uint32_t)(wm + mi * 16 + aRow) * 128 + (uint32_t)(ksi * 32) + aCol;
                ldm_x4(sS + swz(off), a[mi][0], a[mi][1], a[mi][2], a[mi][3]);
            }
#pragma unroll
            for (int mi = 0; mi < 2; mi++)
#pragma unroll
                for (int ng = 0; ng < 4; ng++) {
                    mma16816(acc[mi][ng * 2 + 0], a[mi], bf[ng][0], bf[ng][1]);
                    mma16816(acc[mi][ng * 2 + 1], a[mi], bf[ng][2], bf[ng][3]);
                }
            // --- lo A (same B, same acc) ---
            if (dual) {
#pragma unroll
                for (int mi = 0; mi < 2; mi++) {
                    uint32_t off = (uint32_t)(wm + mi * 16 + aRow) * 128 + (uint32_t)(ksi * 32) + aCol;
                    ldm_x4(sS + 16384 + swz(off), a[mi][0], a[mi][1], a[mi][2], a[mi][3]);
                }
#pragma unroll
                for (int mi = 0; mi < 2; mi++)
#pragma unroll
                    for (int ng = 0; ng < 4; ng++) {
                        mma16816(acc[mi][ng * 2 + 0], a[mi], bf[ng][0], bf[ng][1]);
                        mma16816(acc[mi][ng * 2 + 1], a[mi], bf[ng][2], bf[ng][3]);
                    }
            }
        }
        __syncthreads();
        if (kt + 2 < CLS_NKT) {
            cls_issue_loads(sbase, kt + 2, m0c, n0c, tid);
            cp_commit();
        }
    }

    // epilogue: bias + scatter into (B, T, V); C row m = t*16 + b
#pragma unroll
    for (int mi = 0; mi < 2; mi++) {
#pragma unroll
        for (int ni = 0; ni < 8; ni++) {
            int nloc = wn + ni * 8 + (l & 3) * 2;
            int n = n0c + nloc;
            float bx = biasS[nloc], by = biasS[nloc + 1];
            int m1 = m0c + wm + mi * 16 + (l >> 2);
            int m2 = m1 + 8;
            {
                int t = m1 >> 4, b = m1 & 15;
                float2 v; v.x = acc[mi][ni][0] + bx; v.y = acc[mi][ni][1] + by;
                *(float2*)&out[(size_t)b * ((size_t)TT * VV) + (size_t)t * VV + n] = v;
            }
            {
                int t = m2 >> 4, b = m2 & 15;
                float2 v; v.x = acc[mi][ni][2] + bx; v.y = acc[mi][ni][3] + by;
                *(float2*)&out[(size_t)b * ((size_t)TT * VV) + (size_t)t * VV + n] = v;
            }
        }
    }
}

// ---------------- launch ----------------
extern "C" void kernel_launch(void* const* d_in, const int* in_sizes, int n_in,
                              void* d_out, int out_size)
{
    const float* enc_h  = (const float*)d_in[0];
    const float* enc_c  = (const float*)d_in[1];
    const float* target = (const float*)d_in[2];
    const float* Wih0f = (const float*)d_in[3];
    const float* Whh0f = (const float*)d_in[4];
    const float* bi0f  = (const float*)d_in[5];
    const float* bh0f  = (const float*)d_in[6];
    const float* Wih0b = (const float*)d_in[7];
    const float* Whh0b = (const float*)d_in[8];
    const float* bi0b  = (const float*)d_in[9];
    const float* bh0b  = (const float*)d_in[10];
    const float* Wih1f = (const float*)d_in[11];
    const float* Whh1f = (const float*)d_in[12];
    const float* bi1f  = (const float*)d_in[13];
    const float* bh1f  = (const float*)d_in[14];
    const float* Wih1b = (const float*)d_in[15];
    const float* Whh1b = (const float*)d_in[16];
    const float* bi1b  = (const float*)d_in[17];
    const float* bh1b  = (const float*)d_in[18];
    const float* Wcls  = (const float*)d_in[19];
    const float* bcls  = (const float*)d_in[20];
    float* out = (float*)d_out;

    cudaFuncSetAttribute(rnn_kernel, cudaFuncAttributeMaxDynamicSharedMemorySize, SMEM_BYTES);
    cudaFuncSetAttribute(cls_tc_kernel, cudaFuncAttributeMaxDynamicSharedMemorySize, SMEM_CLS);

    // convert_w also resets the rnn barrier counters (stream-ordered before rnn)
    convert_w_kernel<<<32000, 256>>>(Wcls);           // 32000*1024 f32 -> hi/lo bf16
    rnn_kernel<<<NBLK, NTHR, SMEM_BYTES>>>(
        enc_h, enc_c, target,
        Wih0f, Whh0f, bi0f, bh0f,
        Wih0b, Whh0b, bi0b, bh0b,
        Wih1f, Whh1f, bi1f, bh1f,
        Wih1b, Whh1b, bi1b, bh1b,
        out);
    dim3 g((TT * BB) / 128, VV / 128);                // (32, 250): m fastest
    cls_tc_kernel<<<g, 256, SMEM_CLS>>>(bcls, out);
}